// round 4
// baseline (speedup 1.0000x reference)
#include <cuda_runtime.h>

// Fused conv3x3(SAME) + bias + min-over-K + tanh(tanh(.))
// N=16, C=64, H=W=256, K=64, R=S=3.
//
// Inputs (metadata order): d_in[0]=x [16,64,256,256] f32, d_in[1]=w [64,64,3,3] f32,
//                          d_in[2]=b [64] f32. Output: [16,1,256,256] f32.

#define TILE 16
#define XS_COLS 18          // 16 + 2 halo
#define XS_STRIDE 21        // padded row stride (odd-ish, spreads banks)

// Transposed weights: wt[c][r][s][k], 64*9*64 floats (no device allocs allowed;
// __device__ global is the sanctioned scratch).
__device__ float g_wt[64 * 9 * 64];

__global__ void wt_transpose_kernel(const float* __restrict__ w) {
    int i = blockIdx.x * 256 + threadIdx.x;   // i = k*576 + (c*9 + rs)
    if (i >= 64 * 64 * 9) return;
    int k   = i / 576;
    int crs = i % 576;                        // c*9 + rs
    g_wt[crs * 64 + k] = w[i];
}

__global__ __launch_bounds__(256, 2)
void conv_min_tanh_kernel(const float* __restrict__ x,
                          const float* __restrict__ b,
                          float* __restrict__ out) {
    __shared__ __align__(16) float xs[XS_COLS * XS_STRIDE];   // 18 rows x 21 stride
    __shared__ __align__(16) float ws[9 * 64];                // [rs][k] slice for current c
    __shared__ __align__(16) float red[4 * 64 * 4];           // [g][p][px] min buffer

    const int tid = threadIdx.x;
    const int g   = tid >> 6;          // k-group 0..3  (whole warps share g)
    const int p   = tid & 63;          // pixel group 0..63
    const int py  = p >> 2;            // tile row 0..15
    const int px4 = (p & 3) * 4;       // tile col base 0,4,8,12
    const int k0  = g * 16;

    const int n  = blockIdx.z;
    const int h0 = blockIdx.y * TILE;
    const int w0 = blockIdx.x * TILE;

    float acc[16][4];
    #pragma unroll
    for (int i = 0; i < 16; ++i)
        #pragma unroll
        for (int j = 0; j < 4; ++j)
            acc[i][j] = 0.0f;

    const float* xn = x + (size_t)n * 64 * 256 * 256;

    for (int c = 0; c < 64; ++c) {
        __syncthreads();   // previous iteration's compute done before smem reuse

        // ---- stage x tile (18x18 with halo, zero-padded at image border) ----
        const float* xc = xn + c * 65536;
        for (int i = tid; i < XS_COLS * XS_COLS; i += 256) {
            int row = i / XS_COLS;
            int col = i % XS_COLS;
            int gh  = h0 - 1 + row;
            int gw  = w0 - 1 + col;
            float v = 0.0f;
            if ((unsigned)gh < 256u && (unsigned)gw < 256u)
                v = xc[gh * 256 + gw];
            xs[row * XS_STRIDE + col] = v;
        }
        // ---- stage weight slice wt[c][.][.] : 576 floats ----
        const float* wc = g_wt + c * 576;
        for (int i = tid; i < 576; i += 256) ws[i] = wc[i];

        __syncthreads();

        // ---- compute: 576 FMAs per thread per c ----
        #pragma unroll
        for (int r = 0; r < 3; ++r) {
            float xr[6];
            #pragma unroll
            for (int j = 0; j < 6; ++j)
                xr[j] = xs[(py + r) * XS_STRIDE + px4 + j];
            #pragma unroll
            for (int s = 0; s < 3; ++s) {
                const float4* wp = (const float4*)&ws[(r * 3 + s) * 64 + k0];
                #pragma unroll
                for (int q = 0; q < 4; ++q) {
                    float4 w4 = wp[q];   // broadcast within warp (same g)
                    #pragma unroll
                    for (int px = 0; px < 4; ++px) {
                        float xv = xr[px + s];
                        acc[q * 4 + 0][px] = fmaf(xv, w4.x, acc[q * 4 + 0][px]);
                        acc[q * 4 + 1][px] = fmaf(xv, w4.y, acc[q * 4 + 1][px]);
                        acc[q * 4 + 2][px] = fmaf(xv, w4.z, acc[q * 4 + 2][px]);
                        acc[q * 4 + 3][px] = fmaf(xv, w4.w, acc[q * 4 + 3][px]);
                    }
                }
            }
        }
    }

    // ---- epilogue: bias + min over this thread's 16 channels ----
    float vmin[4];
    #pragma unroll
    for (int px = 0; px < 4; ++px) {
        float v = acc[0][px] + b[k0];
        #pragma unroll
        for (int kk = 1; kk < 16; ++kk)
            v = fminf(v, acc[kk][px] + b[k0 + kk]);
        vmin[px] = v;
    }

    #pragma unroll
    for (int px = 0; px < 4; ++px)
        red[(g * 64 + p) * 4 + px] = vmin[px];
    __syncthreads();

    // ---- min across the 4 k-groups, tanh(tanh), store ----
    if (tid < 64) {
        int pp = tid;
        float4 o;
        float* op = (float*)&o;
        #pragma unroll
        for (int px = 0; px < 4; ++px) {
            float m = red[(0 * 64 + pp) * 4 + px];
            m = fminf(m, red[(1 * 64 + pp) * 4 + px]);
            m = fminf(m, red[(2 * 64 + pp) * 4 + px]);
            m = fminf(m, red[(3 * 64 + pp) * 4 + px]);
            op[px] = tanhf(tanhf(m));
        }
        int pyy  = pp >> 2;
        int pxx4 = (pp & 3) * 4;
        *(float4*)&out[(size_t)n * 65536 + (size_t)(h0 + pyy) * 256 + w0 + pxx4] = o;
    }
}

extern "C" void kernel_launch(void* const* d_in, const int* in_sizes, int n_in,
                              void* d_out, int out_size) {
    const float* x = (const float*)d_in[0];
    const float* w = (const float*)d_in[1];
    const float* b = (const float*)d_in[2];
    float* out = (float*)d_out;

    // Stage 1: transpose weights into [c][r][s][k] layout.
    wt_transpose_kernel<<<(64 * 64 * 9 + 255) / 256, 256>>>(w);

    // Stage 2: fused conv + min + tanh. grid: (wtile, htile, n)
    dim3 grid(256 / TILE, 256 / TILE, 16);
    conv_min_tanh_kernel<<<grid, 256>>>(x, b, out);
}

// round 6
// speedup vs baseline: 7.4908x; 7.4908x over previous
#include <cuda_runtime.h>
#include <cuda_bf16.h>
#include <cstdint>

// Fused conv3x3(SAME)+bias+min_k+tanh(tanh) via warp-level bf16 mma.sync
// (base-ISA tensor path; tcgen05 unavailable: harness targets compute_103).
// N=16, C=64, H=W=256, K=64. x f32 NCHW, w f32 [K,C,3,3], b f32 [64].
// Output f32 [16,1,256,256].

// ---------------- device-global scratch (allocs banned) --------------------
__device__ __nv_bfloat16 g_xt[16u * 256u * 256u * 64u];   // NHWC bf16
__device__ __nv_bfloat16 g_wtb[9 * 64 * 64];              // [rs][k][c]

// ---------------- helpers --------------------------------------------------
__device__ __forceinline__ uint32_t smem_u32(const void* p) {
    uint32_t a;
    asm("{ .reg .u64 t; cvta.to.shared.u64 t, %1; cvt.u32.u64 %0, t; }" : "=r"(a) : "l"(p));
    return a;
}
#define LDSM_X4(r, addr)                                                        \
    asm volatile("ldmatrix.sync.aligned.m8n8.x4.shared.b16 {%0,%1,%2,%3}, [%4];" \
                 : "=r"((r)[0]), "=r"((r)[1]), "=r"((r)[2]), "=r"((r)[3]) : "r"(addr))

__device__ __forceinline__ void mma_bf16(float* d, const uint32_t* a, const uint32_t* b) {
    asm volatile(
        "mma.sync.aligned.m16n8k16.row.col.f32.bf16.bf16.f32 "
        "{%0,%1,%2,%3}, {%4,%5,%6,%7}, {%8,%9}, {%0,%1,%2,%3};"
        : "+f"(d[0]), "+f"(d[1]), "+f"(d[2]), "+f"(d[3])
        : "r"(a[0]), "r"(a[1]), "r"(a[2]), "r"(a[3]), "r"(b[0]), "r"(b[1]));
}

// ---------------- prep: x NCHW f32 -> NHWC bf16 ----------------------------
__global__ void prep_x_kernel(const float* __restrict__ x) {
    __shared__ float tile[64][65];
    const int w0 = blockIdx.x * 64;
    const int n  = blockIdx.y >> 8;
    const int h  = blockIdx.y & 255;
    const int t  = threadIdx.x;

    const float* xp = x + ((size_t)n * 64) * 65536 + (size_t)h * 256;
    const int wl = t & 63, cb = t >> 6;
    #pragma unroll
    for (int pass = 0; pass < 16; ++pass) {
        int c = cb + pass * 4;
        tile[c][wl] = xp[(size_t)c * 65536 + w0 + wl];
    }
    __syncthreads();

    const int c2 = (t & 31) * 2, wb = t >> 5;
    #pragma unroll
    for (int pass = 0; pass < 8; ++pass) {
        int wl2 = wb + pass * 8;
        __nv_bfloat162 v;
        v.x = __float2bfloat16(tile[c2][wl2]);
        v.y = __float2bfloat16(tile[c2 + 1][wl2]);
        size_t o = (((size_t)n * 256 + h) * 256 + w0 + wl2) * 64 + c2;
        *reinterpret_cast<__nv_bfloat162*>(&g_xt[o]) = v;
    }
}

// ---------------- prep: w [K,C,3,3] f32 -> [rs][k][c] bf16 -----------------
__global__ void prep_w_kernel(const float* __restrict__ w) {
    int i = blockIdx.x * 256 + threadIdx.x;     // rs*4096 + k*64 + c
    if (i >= 9 * 64 * 64) return;
    int rs = i >> 12, rem = i & 4095, k = rem >> 6, c = rem & 63;
    g_wtb[i] = __float2bfloat16(w[(size_t)(k * 64 + c) * 9 + rs]);
}

// ---------------- main: implicit GEMM via mma.sync -------------------------
// smem: A window 3 rows x 260 px, 144B/px stride (bank-conflict-free ldmatrix)
//       B: 9 x 64 rows x 144B.  bias: 64 f32.
#define PXS      144                       // padded pixel stride bytes
#define AROW     (260 * PXS)               // 37440
#define SM_A     0
#define SM_B     (3 * AROW)                // 112320
#define BMAT     (64 * PXS)                // 9216
#define SM_BIAS  (SM_B + 9 * BMAT)         // 195264
#define SM_TOTAL (SM_BIAS + 256)           // 195520

__global__ void __launch_bounds__(256, 1)
conv_mma_kernel(const float* __restrict__ bias, float* __restrict__ out) {
    extern __shared__ char smem[];
    const uint32_t sb = smem_u32(smem);
    const int tid = threadIdx.x, wid = tid >> 5, lane = tid & 31;
    const int cq = lane & 3, lrow = lane >> 2;

    const int n = blockIdx.y;
    const int hbase = blockIdx.x * 4;

    // ---- stage B (all 9 taps) + bias, once ----
    for (int i = tid; i < 9 * 64 * 8; i += 256) {       // 4608 uint4
        int rs = i >> 9, rem = i & 511, k = rem >> 3, c16 = rem & 7;
        uint4 v = *reinterpret_cast<const uint4*>(g_wtb + rs * 4096 + k * 64 + c16 * 8);
        *reinterpret_cast<uint4*>(smem + SM_B + rs * BMAT + k * PXS + c16 * 16) = v;
    }
    if (tid < 64) ((float*)(smem + SM_BIAS))[tid] = bias[tid];
    __syncthreads();

    // bias values this thread needs: n = nf*8 + 2*cq + j
    float bv[8][2];
    #pragma unroll
    for (int nf = 0; nf < 8; ++nf) {
        bv[nf][0] = ((const float*)(smem + SM_BIAS))[nf * 8 + 2 * cq + 0];
        bv[nf][1] = ((const float*)(smem + SM_BIAS))[nf * 8 + 2 * cq + 1];
    }

    const __nv_bfloat16* xtn = g_xt + (size_t)n * 256 * 256 * 64;

    // ldmatrix lane-address components
    const uint32_t aLane = (uint32_t)((lane & 15) * PXS + ((lane >> 4) << 4));
    const uint32_t bLane = (uint32_t)(((lane & 7) + ((lane >> 4) << 3)) * PXS
                                      + (((lane >> 3) & 1) << 4));

    for (int hi = 0; hi < 4; ++hi) {
        const int h = hbase + hi;
        __syncthreads();   // previous iteration's ldmatrix done before restage

        // ---- stage A: rows h-1,h,h+1, pixels -1..258 (zero-padded OOB) ----
        for (int i = tid; i < 3 * 260 * 8; i += 256) {   // 6240 uint4
            int row3 = i / 2080, rem = i % 2080, px = rem >> 3, c16 = rem & 7;
            int hh = h - 1 + row3, ww = px - 1;
            uint4 v = make_uint4(0u, 0u, 0u, 0u);
            if ((unsigned)hh < 256u && (unsigned)ww < 256u)
                v = *reinterpret_cast<const uint4*>(xtn + ((size_t)hh * 256 + ww) * 64 + c16 * 8);
            *reinterpret_cast<uint4*>(smem + SM_A + row3 * AROW + px * PXS + c16 * 16) = v;
        }
        __syncthreads();

        float acc[2][8][4];
        #pragma unroll
        for (int mf = 0; mf < 2; ++mf)
            #pragma unroll
            for (int nf = 0; nf < 8; ++nf)
                #pragma unroll
                for (int j = 0; j < 4; ++j) acc[mf][nf][j] = 0.0f;

        #pragma unroll
        for (int rs = 0; rs < 9; ++rs) {
            const int r = rs / 3, s = rs % 3;
            const uint32_t aTap = sb + SM_A + r * AROW + (wid * 32 + s) * PXS + aLane;
            const uint32_t bTap = sb + SM_B + rs * BMAT + bLane;
            #pragma unroll
            for (int kc = 0; kc < 4; ++kc) {
                uint32_t a0[4], a1[4], bb[16];
                LDSM_X4(a0, aTap + kc * 32);
                LDSM_X4(a1, aTap + kc * 32 + 16 * PXS);
                #pragma unroll
                for (int nb = 0; nb < 4; ++nb)
                    LDSM_X4(bb + nb * 4, bTap + kc * 32 + nb * 16 * PXS);
                #pragma unroll
                for (int nb = 0; nb < 4; ++nb) {
                    mma_bf16(acc[0][2 * nb + 0], a0, bb + nb * 4 + 0);
                    mma_bf16(acc[0][2 * nb + 1], a0, bb + nb * 4 + 2);
                    mma_bf16(acc[1][2 * nb + 0], a1, bb + nb * 4 + 0);
                    mma_bf16(acc[1][2 * nb + 1], a1, bb + nb * 4 + 2);
                }
            }
        }

        // ---- epilogue: bias + min over 64 n + tanh(tanh) + store ----
        #pragma unroll
        for (int mf = 0; mf < 2; ++mf) {
            #pragma unroll
            for (int half = 0; half < 2; ++half) {
                float m = acc[mf][0][half * 2 + 0] + bv[0][0];
                m = fminf(m, acc[mf][0][half * 2 + 1] + bv[0][1]);
                #pragma unroll
                for (int nf = 1; nf < 8; ++nf) {
                    m = fminf(m, acc[mf][nf][half * 2 + 0] + bv[nf][0]);
                    m = fminf(m, acc[mf][nf][half * 2 + 1] + bv[nf][1]);
                }
                m = fminf(m, __shfl_xor_sync(0xFFFFFFFFu, m, 1));
                m = fminf(m, __shfl_xor_sync(0xFFFFFFFFu, m, 2));
                if (cq == 0) {
                    int px = wid * 32 + mf * 16 + half * 8 + lrow;
                    out[(size_t)n * 65536 + (size_t)h * 256 + px] = tanhf(tanhf(m));
                }
            }
        }
    }
}

// ---------------- launch ---------------------------------------------------
extern "C" void kernel_launch(void* const* d_in, const int* in_sizes, int n_in,
                              void* d_out, int out_size) {
    const float* x = (const float*)d_in[0];
    const float* w = (const float*)d_in[1];
    const float* b = (const float*)d_in[2];
    float* out = (float*)d_out;

    cudaFuncSetAttribute(conv_mma_kernel,
                         cudaFuncAttributeMaxDynamicSharedMemorySize, SM_TOTAL);

    prep_w_kernel<<<(9 * 64 * 64 + 255) / 256, 256>>>(w);
    prep_x_kernel<<<dim3(4, 4096), 256>>>(x);

    dim3 grid(64, 16);   // (h-strips of 4, n)
    conv_mma_kernel<<<grid, 256, SM_TOTAL>>>(b, out);
}

// round 8
// speedup vs baseline: 8.6992x; 1.1613x over previous
#include <cuda_runtime.h>
#include <cuda_bf16.h>
#include <cstdint>

// Fused conv3x3(SAME)+bias+min_k+tanh(tanh) via warp-level bf16 mma.sync.
// NCHW->NHWC transpose fused into the main kernel (no intermediate tensor).
// N=16, C=64, H=W=256, K=64. x f32 NCHW, w f32 [K,C,3,3], b f32 [64].
// Output f32 [16,1,256,256].

__device__ __nv_bfloat16 g_wtb[9 * 64 * 64];              // [rs][k][c]

__device__ __forceinline__ uint32_t smem_u32(const void* p) {
    uint32_t a;
    asm("{ .reg .u64 t; cvta.to.shared.u64 t, %1; cvt.u32.u64 %0, t; }" : "=r"(a) : "l"(p));
    return a;
}
__device__ __forceinline__ uint32_t pack_bf16x2(float lo, float hi) {
    uint32_t r;
    asm("cvt.rn.bf16x2.f32 %0, %1, %2;" : "=r"(r) : "f"(hi), "f"(lo));
    return r;
}
#define LDSM_X4(r, addr)                                                        \
    asm volatile("ldmatrix.sync.aligned.m8n8.x4.shared.b16 {%0,%1,%2,%3}, [%4];" \
                 : "=r"((r)[0]), "=r"((r)[1]), "=r"((r)[2]), "=r"((r)[3]) : "r"(addr))

__device__ __forceinline__ void mma_bf16(float* d, const uint32_t* a, const uint32_t* b) {
    asm volatile(
        "mma.sync.aligned.m16n8k16.row.col.f32.bf16.bf16.f32 "
        "{%0,%1,%2,%3}, {%4,%5,%6,%7}, {%8,%9}, {%0,%1,%2,%3};"
        : "+f"(d[0]), "+f"(d[1]), "+f"(d[2]), "+f"(d[3])
        : "r"(a[0]), "r"(a[1]), "r"(a[2]), "r"(a[3]), "r"(b[0]), "r"(b[1]));
}

// ---------------- prep: w [K,C,3,3] f32 -> [rs][k][c] bf16 -----------------
__global__ void prep_w_kernel(const float* __restrict__ w) {
    int i = blockIdx.x * 256 + threadIdx.x;     // rs*4096 + k*64 + c
    if (i >= 9 * 64 * 64) return;
    int rs = i >> 12, rem = i & 4095, k = rem >> 6, c = rem & 63;
    g_wtb[i] = __float2bfloat16(w[(size_t)(k * 64 + c) * 9 + rs]);
}

// ---------------- main kernel ----------------------------------------------
// smem: A ring: 4 row-slots x 260 px x 144B (pad keeps ldsm conflict-free)
//       B: 9 taps x [64 k x 128B] XOR-swizzled.  bias: 64 f32.
#define PXS      144
#define AROW     (260 * PXS)               // 37440
#define SM_A     0
#define SM_B     (4 * AROW)                // 149760
#define SM_BIAS  (SM_B + 9 * 8192)         // 223488
#define SM_TOTAL (SM_BIAS + 256)           // 223744

__global__ void __launch_bounds__(256, 1)
conv_mma_kernel(const float* __restrict__ x,
                const float* __restrict__ bias, float* __restrict__ out) {
    extern __shared__ char smem[];
    const uint32_t sb = smem_u32(smem);
    const int tid = threadIdx.x, wid = tid >> 5, lane = tid & 31;
    const int cq = lane & 3, lrow = lane >> 2;

    const int n  = blockIdx.y;
    const int hs = blockIdx.x * 8;
    const float* xn = x + (size_t)n * 64 * 65536;

    // ---- stage B (swizzled) + bias, once ----
    for (int i = tid; i < 9 * 64 * 8; i += 256) {
        int rs = i >> 9, rem = i & 511, k = rem >> 3, c16 = rem & 7;
        uint4 v = *reinterpret_cast<const uint4*>(g_wtb + rs * 4096 + k * 64 + c16 * 8);
        uint32_t off = (uint32_t)(k * 128 + c16 * 16);
        off ^= (off >> 3) & 0x70;
        *reinterpret_cast<uint4*>(smem + SM_B + rs * 8192 + off) = v;
    }
    if (tid < 64) ((float*)(smem + SM_BIAS))[tid] = bias[tid];
    __syncthreads();

    float bv[8][2];
    #pragma unroll
    for (int nf = 0; nf < 8; ++nf) {
        bv[nf][0] = ((const float*)(smem + SM_BIAS))[nf * 8 + 2 * cq + 0];
        bv[nf][1] = ((const float*)(smem + SM_BIAS))[nf * 8 + 2 * cq + 1];
    }

    // staging lambda: NCHW f32 -> A-window [px][c] bf16, fused transpose.
    // warp wid owns c-group wid*8; lane owns pixel chunk*32-1+lane.
    auto stage_row = [&](int hh) {
        const int slot = (hh + 4) & 3;
        const int c0 = wid * 8;
        const bool hok = (unsigned)hh < 256u;
        const float* src = xn + (size_t)c0 * 65536 + (size_t)(hok ? hh : 0) * 256;
        #pragma unroll
        for (int chunk = 0; chunk < 9; ++chunk) {
            int px = chunk * 32 - 1 + lane;
            bool pok = hok && (unsigned)px < 256u;
            float v[8];
            #pragma unroll
            for (int j = 0; j < 8; ++j)
                v[j] = pok ? src[j * 65536 + px] : 0.0f;
            if (px <= 258) {
                uint4 pk;
                pk.x = pack_bf16x2(v[0], v[1]);
                pk.y = pack_bf16x2(v[2], v[3]);
                pk.z = pack_bf16x2(v[4], v[5]);
                pk.w = pack_bf16x2(v[6], v[7]);
                *reinterpret_cast<uint4*>(smem + SM_A + slot * AROW + (px + 1) * PXS + c0 * 2) = pk;
            }
        }
    };

    // per-warp output mapping: 8 warps x 64 px = 512 px = 2 rows
    const int hoff    = wid >> 2;            // 0 or 1: row within pair
    const int pxwbase = (wid & 3) * 64;
    const uint32_t aLane = (uint32_t)((lane & 15) * PXS + ((lane >> 4) << 4));
    const int rowb = (lane & 7) + ((lane >> 4) << 3);
    const int colb = ((lane >> 3) & 1) << 4;

    for (int h0 = hs; h0 < hs + 8; h0 += 2) {
        __syncthreads();                     // prior compute done before slot reuse
        if (h0 == hs) {
            stage_row(h0 - 1); stage_row(h0); stage_row(h0 + 1); stage_row(h0 + 2);
        } else {
            stage_row(h0 + 1); stage_row(h0 + 2);
        }
        __syncthreads();

        const int hrow = h0 + hoff;

        float acc[4][8][4];
        #pragma unroll
        for (int mf = 0; mf < 4; ++mf)
            #pragma unroll
            for (int nf = 0; nf < 8; ++nf)
                #pragma unroll
                for (int j = 0; j < 4; ++j) acc[mf][nf][j] = 0.0f;

        #pragma unroll 1
        for (int rs = 0; rs < 9; ++rs) {
            const int r = rs / 3, s = rs % 3;
            const int slot = (hrow + 3 + r) & 3;      // row hrow-1+r
            const uint32_t aBase = sb + SM_A + slot * AROW + (pxwbase + s) * PXS + aLane;
            const uint32_t bBase = sb + SM_B + rs * 8192;
            #pragma unroll
            for (int kc = 0; kc < 4; ++kc) {
                uint32_t a[4][4];
                #pragma unroll
                for (int mf = 0; mf < 4; ++mf)
                    LDSM_X4(a[mf], aBase + mf * (16 * PXS) + kc * 32);
                uint32_t bb[16];
                #pragma unroll
                for (int nb = 0; nb < 4; ++nb) {
                    uint32_t off = (uint32_t)((rowb + nb * 16) * 128 + colb + kc * 32);
                    off ^= (off >> 3) & 0x70;
                    LDSM_X4(bb + nb * 4, bBase + off);
                }
                #pragma unroll
                for (int nb = 0; nb < 4; ++nb)
                    #pragma unroll
                    for (int mf = 0; mf < 4; ++mf) {
                        mma_bf16(acc[mf][2 * nb + 0], a[mf], bb + nb * 4 + 0);
                        mma_bf16(acc[mf][2 * nb + 1], a[mf], bb + nb * 4 + 2);
                    }
            }
        }

        // ---- epilogue: bias + min over 64 k + tanh(tanh) + store ----
        #pragma unroll
        for (int mf = 0; mf < 4; ++mf) {
            #pragma unroll
            for (int half = 0; half < 2; ++half) {
                float m = acc[mf][0][half * 2 + 0] + bv[0][0];
                m = fminf(m, acc[mf][0][half * 2 + 1] + bv[0][1]);
                #pragma unroll
                for (int nf = 1; nf < 8; ++nf) {
                    m = fminf(m, acc[mf][nf][half * 2 + 0] + bv[nf][0]);
                    m = fminf(m, acc[mf][nf][half * 2 + 1] + bv[nf][1]);
                }
                m = fminf(m, __shfl_xor_sync(0xFFFFFFFFu, m, 1));
                m = fminf(m, __shfl_xor_sync(0xFFFFFFFFu, m, 2));
                if (cq == 0) {
                    int px = pxwbase + mf * 16 + half * 8 + lrow;
                    out[(size_t)n * 65536 + (size_t)hrow * 256 + px] = tanhf(tanhf(m));
                }
            }
        }
    }
}

// ---------------- launch ---------------------------------------------------
extern "C" void kernel_launch(void* const* d_in, const int* in_sizes, int n_in,
                              void* d_out, int out_size) {
    const float* x = (const float*)d_in[0];
    const float* w = (const float*)d_in[1];
    const float* b = (const float*)d_in[2];
    float* out = (float*)d_out;

    cudaFuncSetAttribute(conv_mma_kernel,
                         cudaFuncAttributeMaxDynamicSharedMemorySize, SM_TOTAL);

    prep_w_kernel<<<(9 * 64 * 64 + 255) / 256, 256>>>(w);

    dim3 grid(32, 16);   // (h-strips of 8, n)
    conv_mma_kernel<<<grid, 256, SM_TOTAL>>>(x, b, out);
}

// round 9
// speedup vs baseline: 8.7002x; 1.0001x over previous
#include <cuda_runtime.h>
#include <cuda_bf16.h>
#include <cstdint>

// Fused conv3x3(SAME)+bias+min_k+tanh(tanh) via warp-level bf16 mma.sync.
// Pipelined: row h+2 gmem loads issue before the MMA block, STS after it.
// N=16, C=64, H=W=256, K=64. x f32 NCHW, w f32 [K,C,3,3], b f32 [64].

__device__ __nv_bfloat16 g_wtb[9 * 64 * 64];              // [rs][k][c]

__device__ __forceinline__ uint32_t smem_u32(const void* p) {
    uint32_t a;
    asm("{ .reg .u64 t; cvta.to.shared.u64 t, %1; cvt.u32.u64 %0, t; }" : "=r"(a) : "l"(p));
    return a;
}
__device__ __forceinline__ uint32_t pack_bf16x2(float lo, float hi) {
    uint32_t r;
    asm("cvt.rn.bf16x2.f32 %0, %1, %2;" : "=r"(r) : "f"(hi), "f"(lo));
    return r;
}
#define LDSM_X4(r, addr)                                                        \
    asm volatile("ldmatrix.sync.aligned.m8n8.x4.shared.b16 {%0,%1,%2,%3}, [%4];" \
                 : "=r"((r)[0]), "=r"((r)[1]), "=r"((r)[2]), "=r"((r)[3]) : "r"(addr))

__device__ __forceinline__ void mma_bf16(float* d, const uint32_t* a, const uint32_t* b) {
    asm volatile(
        "mma.sync.aligned.m16n8k16.row.col.f32.bf16.bf16.f32 "
        "{%0,%1,%2,%3}, {%4,%5,%6,%7}, {%8,%9}, {%0,%1,%2,%3};"
        : "+f"(d[0]), "+f"(d[1]), "+f"(d[2]), "+f"(d[3])
        : "r"(a[0]), "r"(a[1]), "r"(a[2]), "r"(a[3]), "r"(b[0]), "r"(b[1]));
}

// ---------------- prep: w [K,C,3,3] f32 -> [rs][k][c] bf16 -----------------
__global__ void prep_w_kernel(const float* __restrict__ w) {
    int i = blockIdx.x * 256 + threadIdx.x;     // rs*4096 + k*64 + c
    if (i >= 9 * 64 * 64) return;
    int rs = i >> 12, rem = i & 4095, k = rem >> 6, c = rem & 63;
    g_wtb[i] = __float2bfloat16(w[(size_t)(k * 64 + c) * 9 + rs]);
}

// ---------------- main kernel ----------------------------------------------
#define PXS      144
#define AROW     (260 * PXS)               // 37440
#define SM_A     0
#define SM_B     (4 * AROW)                // 149760
#define SM_BIAS  (SM_B + 9 * 8192)         // 223488
#define SM_TOTAL (SM_BIAS + 256)           // 223744

__global__ void __launch_bounds__(256, 1)
conv_mma_kernel(const float* __restrict__ x,
                const float* __restrict__ bias, float* __restrict__ out) {
    extern __shared__ char smem[];
    const uint32_t sb = smem_u32(smem);
    const int tid = threadIdx.x, wid = tid >> 5, lane = tid & 31;
    const int cq = lane & 3, lrow = lane >> 2;

    const int n  = blockIdx.y;
    const int hs = blockIdx.x * 8;
    const float* xn = x + (size_t)n * 64 * 65536;

    // ---- stage B (swizzled) + bias, once ----
    for (int i = tid; i < 9 * 64 * 8; i += 256) {
        int rs = i >> 9, rem = i & 511, k = rem >> 3, c16 = rem & 7;
        uint4 v = *reinterpret_cast<const uint4*>(g_wtb + rs * 4096 + k * 64 + c16 * 8);
        uint32_t off = (uint32_t)(k * 128 + c16 * 16);
        off ^= (off >> 3) & 0x70;
        *reinterpret_cast<uint4*>(smem + SM_B + rs * 8192 + off) = v;
    }
    if (tid < 64) ((float*)(smem + SM_BIAS))[tid] = bias[tid];

    const int c0 = wid * 8;        // staging: warp owns 8 channels

    // immediate stage (LDG+pack+STS) for the first 3 window rows
    auto stage_row = [&](int hh) {
        const int slot = (hh + 4) & 3;
        const bool hok = (unsigned)hh < 256u;
        const float* src = xn + (size_t)c0 * 65536 + (size_t)(hok ? hh : 0) * 256;
        #pragma unroll
        for (int chunk = 0; chunk < 9; ++chunk) {
            int px = chunk * 32 - 1 + lane;
            bool pok = hok && (unsigned)px < 256u;
            float v[8];
            #pragma unroll
            for (int j = 0; j < 8; ++j)
                v[j] = pok ? src[j * 65536 + px] : 0.0f;
            if (px <= 258) {
                uint4 pk;
                pk.x = pack_bf16x2(v[0], v[1]);
                pk.y = pack_bf16x2(v[2], v[3]);
                pk.z = pack_bf16x2(v[4], v[5]);
                pk.w = pack_bf16x2(v[6], v[7]);
                *reinterpret_cast<uint4*>(smem + SM_A + slot * AROW + (px + 1) * PXS + c0 * 2) = pk;
            }
        }
    };
    stage_row(hs - 1); stage_row(hs); stage_row(hs + 1);

    __syncthreads();

    float bv[8][2];
    #pragma unroll
    for (int nf = 0; nf < 8; ++nf) {
        bv[nf][0] = ((const float*)(smem + SM_BIAS))[nf * 8 + 2 * cq + 0];
        bv[nf][1] = ((const float*)(smem + SM_BIAS))[nf * 8 + 2 * cq + 1];
    }

    // compute mapping: 8 warps x 32 px = 256 px = 1 row per iteration
    const int pxwbase = wid * 32;
    const uint32_t aLane = (uint32_t)((lane & 15) * PXS + ((lane >> 4) << 4));
    const int rowb = (lane & 7) + ((lane >> 4) << 3);
    const int colb = ((lane >> 3) & 1) << 4;

    for (int h = hs; h < hs + 8; ++h) {
        // ---- issue prefetch LDGs for row h+2 (consumed after MMA) ----
        const int hh = h + 2;
        const bool hok = (unsigned)hh < 256u;
        const float* src = xn + (size_t)c0 * 65536 + (size_t)(hok ? hh : 0) * 256;
        float pf[9][8];
        #pragma unroll
        for (int chunk = 0; chunk < 9; ++chunk) {
            int px = chunk * 32 - 1 + lane;
            bool pok = hok && (unsigned)px < 256u;
            #pragma unroll
            for (int j = 0; j < 8; ++j)
                pf[chunk][j] = pok ? src[j * 65536 + px] : 0.0f;
        }

        // ---- MMA block: rows h-1..h+1 ----
        float acc[2][8][4];
        #pragma unroll
        for (int mf = 0; mf < 2; ++mf)
            #pragma unroll
            for (int nf = 0; nf < 8; ++nf)
                #pragma unroll
                for (int j = 0; j < 4; ++j) acc[mf][nf][j] = 0.0f;

        #pragma unroll 1
        for (int rs = 0; rs < 9; ++rs) {
            const int r = rs / 3, s = rs % 3;
            const int slot = (h + 3 + r) & 3;          // row h-1+r
            const uint32_t aBase = sb + SM_A + slot * AROW + (pxwbase + s) * PXS + aLane;
            const uint32_t bBase = sb + SM_B + rs * 8192;
            #pragma unroll
            for (int kc = 0; kc < 4; ++kc) {
                uint32_t a[2][4];
                #pragma unroll
                for (int mf = 0; mf < 2; ++mf)
                    LDSM_X4(a[mf], aBase + mf * (16 * PXS) + kc * 32);
                uint32_t bb[16];
                #pragma unroll
                for (int nb = 0; nb < 4; ++nb) {
                    uint32_t off = (uint32_t)((rowb + nb * 16) * 128 + colb + kc * 32);
                    off ^= (off >> 3) & 0x70;
                    LDSM_X4(bb + nb * 4, bBase + off);
                }
                #pragma unroll
                for (int nb = 0; nb < 4; ++nb)
                    #pragma unroll
                    for (int mf = 0; mf < 2; ++mf) {
                        mma_bf16(acc[mf][2 * nb + 0], a[mf], bb + nb * 4 + 0);
                        mma_bf16(acc[mf][2 * nb + 1], a[mf], bb + nb * 4 + 2);
                    }
            }
        }

        // ---- epilogue: bias + min over 64 k + tanh(tanh) + store row h ----
        #pragma unroll
        for (int mf = 0; mf < 2; ++mf) {
            #pragma unroll
            for (int half = 0; half < 2; ++half) {
                float m = acc[mf][0][half * 2 + 0] + bv[0][0];
                m = fminf(m, acc[mf][0][half * 2 + 1] + bv[0][1]);
                #pragma unroll
                for (int nf = 1; nf < 8; ++nf) {
                    m = fminf(m, acc[mf][nf][half * 2 + 0] + bv[nf][0]);
                    m = fminf(m, acc[mf][nf][half * 2 + 1] + bv[nf][1]);
                }
                m = fminf(m, __shfl_xor_sync(0xFFFFFFFFu, m, 1));
                m = fminf(m, __shfl_xor_sync(0xFFFFFFFFu, m, 2));
                if (cq == 0) {
                    int px = pxwbase + mf * 16 + half * 8 + lrow;
                    out[(size_t)n * 65536 + (size_t)h * 256 + px] = tanhf(tanhf(m));
                }
            }
        }

        // ---- pack + STS prefetched row h+2 (slot == slot(h-2): not in use) --
        {
            const int slot = (hh + 4) & 3;
            #pragma unroll
            for (int chunk = 0; chunk < 9; ++chunk) {
                int px = chunk * 32 - 1 + lane;
                if (px <= 258) {
                    uint4 pk;
                    pk.x = pack_bf16x2(pf[chunk][0], pf[chunk][1]);
                    pk.y = pack_bf16x2(pf[chunk][2], pf[chunk][3]);
                    pk.z = pack_bf16x2(pf[chunk][4], pf[chunk][5]);
                    pk.w = pack_bf16x2(pf[chunk][6], pf[chunk][7]);
                    *reinterpret_cast<uint4*>(smem + SM_A + slot * AROW + (px + 1) * PXS + c0 * 2) = pk;
                }
            }
        }
        __syncthreads();   // row h+2 visible + all warps past iter-h MMA
    }
}

// ---------------- launch ---------------------------------------------------
extern "C" void kernel_launch(void* const* d_in, const int* in_sizes, int n_in,
                              void* d_out, int out_size) {
    const float* x = (const float*)d_in[0];
    const float* w = (const float*)d_in[1];
    const float* b = (const float*)d_in[2];
    float* out = (float*)d_out;

    cudaFuncSetAttribute(conv_mma_kernel,
                         cudaFuncAttributeMaxDynamicSharedMemorySize, SM_TOTAL);

    prep_w_kernel<<<(9 * 64 * 64 + 255) / 256, 256>>>(w);

    dim3 grid(32, 16);   // (h-strips of 8, n)
    conv_mma_kernel<<<grid, 256, SM_TOTAL>>>(x, b, out);
}

// round 10
// speedup vs baseline: 8.8441x; 1.0165x over previous
#include <cuda_runtime.h>
#include <cuda_bf16.h>
#include <cstdint>

// Fused conv3x3(SAME)+bias+min_k+tanh(tanh) via warp-level bf16 mma.sync.
// 512 threads (16 warps) per CTA for latency hiding; ring-4 row window.
// N=16, C=64, H=W=256, K=64. x f32 NCHW, w f32 [K,C,3,3], b f32 [64].

__device__ __nv_bfloat16 g_wtb[9 * 64 * 64];              // [rs][k][c]

__device__ __forceinline__ uint32_t smem_u32(const void* p) {
    uint32_t a;
    asm("{ .reg .u64 t; cvta.to.shared.u64 t, %1; cvt.u32.u64 %0, t; }" : "=r"(a) : "l"(p));
    return a;
}
__device__ __forceinline__ uint32_t pack_bf16x2(float lo, float hi) {
    uint32_t r;
    asm("cvt.rn.bf16x2.f32 %0, %1, %2;" : "=r"(r) : "f"(hi), "f"(lo));
    return r;
}
#define LDSM_X4(r, addr)                                                        \
    asm volatile("ldmatrix.sync.aligned.m8n8.x4.shared.b16 {%0,%1,%2,%3}, [%4];" \
                 : "=r"((r)[0]), "=r"((r)[1]), "=r"((r)[2]), "=r"((r)[3]) : "r"(addr))

__device__ __forceinline__ void mma_bf16(float* d, const uint32_t* a, const uint32_t* b) {
    asm volatile(
        "mma.sync.aligned.m16n8k16.row.col.f32.bf16.bf16.f32 "
        "{%0,%1,%2,%3}, {%4,%5,%6,%7}, {%8,%9}, {%0,%1,%2,%3};"
        : "+f"(d[0]), "+f"(d[1]), "+f"(d[2]), "+f"(d[3])
        : "r"(a[0]), "r"(a[1]), "r"(a[2]), "r"(a[3]), "r"(b[0]), "r"(b[1]));
}

// ---------------- prep: w [K,C,3,3] f32 -> [rs][k][c] bf16 -----------------
__global__ void prep_w_kernel(const float* __restrict__ w) {
    int i = blockIdx.x * 256 + threadIdx.x;     // rs*4096 + k*64 + c
    if (i >= 9 * 64 * 64) return;
    int rs = i >> 12, rem = i & 4095, k = rem >> 6, c = rem & 63;
    g_wtb[i] = __float2bfloat16(w[(size_t)(k * 64 + c) * 9 + rs]);
}

// ---------------- main kernel ----------------------------------------------
#define PXS      144
#define AROW     (260 * PXS)               // 37440
#define SM_A     0
#define SM_B     (4 * AROW)                // 149760
#define SM_BIAS  (SM_B + 9 * 8192)         // 223488
#define SM_TOTAL (SM_BIAS + 256)           // 223744

__global__ void __launch_bounds__(512, 1)
conv_mma_kernel(const float* __restrict__ x,
                const float* __restrict__ bias, float* __restrict__ out) {
    extern __shared__ char smem[];
    const uint32_t sb = smem_u32(smem);
    const int tid = threadIdx.x, wid = tid >> 5, lane = tid & 31;
    const int cq = lane & 3, lrow = lane >> 2;

    const int n  = blockIdx.y;
    const int hs = blockIdx.x * 8;
    const float* xn = x + (size_t)n * 64 * 65536;

    // ---- stage B (swizzled) + bias, once ----
    for (int i = tid; i < 9 * 64 * 8; i += 512) {
        int rs = i >> 9, rem = i & 511, k = rem >> 3, c16 = rem & 7;
        uint4 v = *reinterpret_cast<const uint4*>(g_wtb + rs * 4096 + k * 64 + c16 * 8);
        uint32_t off = (uint32_t)(k * 128 + c16 * 16);
        off ^= (off >> 3) & 0x70;
        *reinterpret_cast<uint4*>(smem + SM_B + rs * 8192 + off) = v;
    }
    if (tid < 64) ((float*)(smem + SM_BIAS))[tid] = bias[tid];

    // stage one (row, 8-channel group): LDG f32 -> pack bf16x2 -> STS
    auto stage_row_c = [&](int hh, int c0) {
        const int slot = (hh + 4) & 3;
        const bool hok = (unsigned)hh < 256u;
        const float* src = xn + (size_t)c0 * 65536 + (size_t)(hok ? hh : 0) * 256;
        #pragma unroll
        for (int chunk = 0; chunk < 9; ++chunk) {
            int px = chunk * 32 - 1 + lane;
            bool pok = hok && (unsigned)px < 256u;
            float v[8];
            #pragma unroll
            for (int j = 0; j < 8; ++j)
                v[j] = pok ? src[j * 65536 + px] : 0.0f;
            if (px <= 258) {
                uint4 pk;
                pk.x = pack_bf16x2(v[0], v[1]);
                pk.y = pack_bf16x2(v[2], v[3]);
                pk.z = pack_bf16x2(v[4], v[5]);
                pk.w = pack_bf16x2(v[6], v[7]);
                *reinterpret_cast<uint4*>(smem + SM_A + slot * AROW + (px + 1) * PXS + c0 * 2) = pk;
            }
        }
    };

    // initial window: rows hs-1 .. hs+2.  16 warps x 2 tasks = 4 rows x 8 cgroups
    #pragma unroll
    for (int q = 0; q < 2; ++q)
        stage_row_c(hs - 1 + (wid & 3), ((wid >> 2) + q * 4) * 8);
    __syncthreads();

    // compute mapping: 16 warps -> 2 rows x 256 px per iteration
    const int hoff    = wid & 1;
    const int pxwbase = (wid >> 1) * 32;
    const uint32_t aLane = (uint32_t)((lane & 15) * PXS + ((lane >> 4) << 4));
    const int rowb = (lane & 7) + ((lane >> 4) << 3);
    const int colb = ((lane >> 3) & 1) << 4;
    const float* bs = (const float*)(smem + SM_BIAS);

    for (int hp = hs; hp < hs + 8; hp += 2) {
        const int hrow = hp + hoff;

        float acc[2][8][4];
        #pragma unroll
        for (int mf = 0; mf < 2; ++mf)
            #pragma unroll
            for (int nf = 0; nf < 8; ++nf)
                #pragma unroll
                for (int j = 0; j < 4; ++j) acc[mf][nf][j] = 0.0f;

        #pragma unroll 1
        for (int rs = 0; rs < 9; ++rs) {
            const int r = rs / 3, s = rs % 3;
            const int slot = (hrow + 3 + r) & 3;          // row hrow-1+r
            const uint32_t aBase = sb + SM_A + slot * AROW + (pxwbase + s) * PXS + aLane;
            const uint32_t bBase = sb + SM_B + rs * 8192;
            #pragma unroll
            for (int kc = 0; kc < 4; ++kc) {
                uint32_t a[2][4];
                #pragma unroll
                for (int mf = 0; mf < 2; ++mf)
                    LDSM_X4(a[mf], aBase + mf * (16 * PXS) + kc * 32);
                uint32_t bb[16];
                #pragma unroll
                for (int nb = 0; nb < 4; ++nb) {
                    uint32_t off = (uint32_t)((rowb + nb * 16) * 128 + colb + kc * 32);
                    off ^= (off >> 3) & 0x70;
                    LDSM_X4(bb + nb * 4, bBase + off);
                }
                #pragma unroll
                for (int nb = 0; nb < 4; ++nb)
                    #pragma unroll
                    for (int mf = 0; mf < 2; ++mf) {
                        mma_bf16(acc[mf][2 * nb + 0], a[mf], bb + nb * 4 + 0);
                        mma_bf16(acc[mf][2 * nb + 1], a[mf], bb + nb * 4 + 2);
                    }
            }
        }

        // ---- epilogue: bias + min over 64 k + tanh(tanh) + store ----
        #pragma unroll
        for (int mf = 0; mf < 2; ++mf) {
            #pragma unroll
            for (int half = 0; half < 2; ++half) {
                float m = acc[mf][0][half * 2 + 0] + bs[2 * cq + 0];
                m = fminf(m, acc[mf][0][half * 2 + 1] + bs[2 * cq + 1]);
                #pragma unroll
                for (int nf = 1; nf < 8; ++nf) {
                    m = fminf(m, acc[mf][nf][half * 2 + 0] + bs[nf * 8 + 2 * cq + 0]);
                    m = fminf(m, acc[mf][nf][half * 2 + 1] + bs[nf * 8 + 2 * cq + 1]);
                }
                m = fminf(m, __shfl_xor_sync(0xFFFFFFFFu, m, 1));
                m = fminf(m, __shfl_xor_sync(0xFFFFFFFFu, m, 2));
                if (cq == 0) {
                    int px = pxwbase + mf * 16 + half * 8 + lrow;
                    out[(size_t)n * 65536 + (size_t)hrow * 256 + px] = tanhf(tanhf(m));
                }
            }
        }

        __syncthreads();                     // all A-window reads complete
        if (hp + 2 < hs + 8) {
            // stage rows hp+3, hp+4 into the two freed slots
            stage_row_c(hp + 3 + (wid & 1), ((wid >> 1) & 7) * 8);
            __syncthreads();
        }
    }
}

// ---------------- launch ---------------------------------------------------
extern "C" void kernel_launch(void* const* d_in, const int* in_sizes, int n_in,
                              void* d_out, int out_size) {
    const float* x = (const float*)d_in[0];
    const float* w = (const float*)d_in[1];
    const float* b = (const float*)d_in[2];
    float* out = (float*)d_out;

    cudaFuncSetAttribute(conv_mma_kernel,
                         cudaFuncAttributeMaxDynamicSharedMemorySize, SM_TOTAL);

    prep_w_kernel<<<(9 * 64 * 64 + 255) / 256, 256>>>(w);

    dim3 grid(32, 16);   // (h-strips of 8, n)
    conv_mma_kernel<<<grid, 512, SM_TOTAL>>>(x, b, out);
}

// round 11
// speedup vs baseline: 10.1998x; 1.1533x over previous
#include <cuda_runtime.h>
#include <cuda_bf16.h>
#include <cstdint>

// Fused conv3x3(SAME)+bias+min_k+tanh(tanh) via warp-level bf16 mma.sync.
// Phase-overlapped: staging for rows h+3/h+4 happens inside the tap loop,
// gated by named barriers placed where the target ring slots go dead.
// N=16, C=64, H=W=256, K=64. x f32 NCHW, w f32 [K,C,3,3], b f32 [64].

__device__ __nv_bfloat16 g_wtb[9 * 64 * 64];              // [rs][k][c]

__device__ __forceinline__ uint32_t smem_u32(const void* p) {
    uint32_t a;
    asm("{ .reg .u64 t; cvta.to.shared.u64 t, %1; cvt.u32.u64 %0, t; }" : "=r"(a) : "l"(p));
    return a;
}
__device__ __forceinline__ uint32_t pack_bf16x2(float lo, float hi) {
    uint32_t r;
    asm("cvt.rn.bf16x2.f32 %0, %1, %2;" : "=r"(r) : "f"(hi), "f"(lo));
    return r;
}
#define LDSM_X4(r, addr)                                                        \
    asm volatile("ldmatrix.sync.aligned.m8n8.x4.shared.b16 {%0,%1,%2,%3}, [%4];" \
                 : "=r"((r)[0]), "=r"((r)[1]), "=r"((r)[2]), "=r"((r)[3]) : "r"(addr))
#define BAR_SYNC(id) asm volatile("bar.sync %0, 512;" :: "r"(id) : "memory")

__device__ __forceinline__ void mma_bf16(float* d, const uint32_t* a, const uint32_t* b) {
    asm volatile(
        "mma.sync.aligned.m16n8k16.row.col.f32.bf16.bf16.f32 "
        "{%0,%1,%2,%3}, {%4,%5,%6,%7}, {%8,%9}, {%0,%1,%2,%3};"
        : "+f"(d[0]), "+f"(d[1]), "+f"(d[2]), "+f"(d[3])
        : "r"(a[0]), "r"(a[1]), "r"(a[2]), "r"(a[3]), "r"(b[0]), "r"(b[1]));
}

// ---------------- prep: w [K,C,3,3] f32 -> [rs][k][c] bf16 -----------------
__global__ void prep_w_kernel(const float* __restrict__ w) {
    int i = blockIdx.x * 256 + threadIdx.x;     // rs*4096 + k*64 + c
    if (i >= 9 * 64 * 64) return;
    int rs = i >> 12, rem = i & 4095, k = rem >> 6, c = rem & 63;
    g_wtb[i] = __float2bfloat16(w[(size_t)(k * 64 + c) * 9 + rs]);
}

// ---------------- main kernel ----------------------------------------------
#define PXS      144
#define AROW     (260 * PXS)               // 37440
#define SM_A     0
#define SM_B     (4 * AROW)                // 149760
#define SM_BIAS  (SM_B + 9 * 8192)         // 223488
#define SM_TOTAL (SM_BIAS + 256)           // 223744

__global__ void __launch_bounds__(512, 1)
conv_mma_kernel(const float* __restrict__ x,
                const float* __restrict__ bias, float* __restrict__ out) {
    extern __shared__ char smem[];
    const uint32_t sb = smem_u32(smem);
    const int tid = threadIdx.x, wid = tid >> 5, lane = tid & 31;
    const int cq = lane & 3, lrow = lane >> 2;

    const int n  = blockIdx.y;
    const int hs = blockIdx.x * 8;
    const float* xn = x + (size_t)n * 64 * 65536;

    // ---- stage B (swizzled) + bias, once ----
    for (int i = tid; i < 9 * 64 * 8; i += 512) {
        int rs = i >> 9, rem = i & 511, k = rem >> 3, c16 = rem & 7;
        uint4 v = *reinterpret_cast<const uint4*>(g_wtb + rs * 4096 + k * 64 + c16 * 8);
        uint32_t off = (uint32_t)(k * 128 + c16 * 16);
        off ^= (off >> 3) & 0x70;
        *reinterpret_cast<uint4*>(smem + SM_B + rs * 8192 + off) = v;
    }
    if (tid < 64) ((float*)(smem + SM_BIAS))[tid] = bias[tid];

    // full-row staging helper (prologue only)
    auto stage_row_c = [&](int hh, int c0) {
        const int slot = (hh + 4) & 3;
        const bool hok = (unsigned)hh < 256u;
        const float* src = xn + (size_t)c0 * 65536 + (size_t)(hok ? hh : 0) * 256;
        #pragma unroll
        for (int chunk = 0; chunk < 9; ++chunk) {
            int px = chunk * 32 - 1 + lane;
            bool pok = hok && (unsigned)px < 256u;
            float v[8];
            #pragma unroll
            for (int j = 0; j < 8; ++j)
                v[j] = pok ? src[j * 65536 + px] : 0.0f;
            if (px <= 258) {
                uint4 pk;
                pk.x = pack_bf16x2(v[0], v[1]);
                pk.y = pack_bf16x2(v[2], v[3]);
                pk.z = pack_bf16x2(v[4], v[5]);
                pk.w = pack_bf16x2(v[6], v[7]);
                *reinterpret_cast<uint4*>(smem + SM_A + slot * AROW + (px + 1) * PXS + c0 * 2) = pk;
            }
        }
    };

    // initial window: rows hs-1 .. hs+2 (16 warps x 2 tasks = 4 rows x 8 cgroups)
    #pragma unroll
    for (int q = 0; q < 2; ++q)
        stage_row_c(hs - 1 + (wid & 3), ((wid >> 2) + q * 4) * 8);
    __syncthreads();

    // compute mapping: 16 warps -> 2 rows x 256 px per iteration
    const int hoff    = wid & 1;
    const int pxwbase = (wid >> 1) * 32;
    const uint32_t aLane = (uint32_t)((lane & 15) * PXS + ((lane >> 4) << 4));
    const int rowb = (lane & 7) + ((lane >> 4) << 3);
    const int colb = ((lane >> 3) & 1) << 4;
    const float* bs = (const float*)(smem + SM_BIAS);

    // staging role for the overlapped phase
    const bool grpA = (wid < 8);

    for (int hp = hs; hp < hs + 8; hp += 2) {
        const int hrow = hp + hoff;
        const bool do_stage = (hp + 2 < hs + 8);

        const int  srow  = hp + (grpA ? 3 : 4);
        const int  sc0   = (grpA ? wid : wid - 8) * 8;
        const bool rowok = (unsigned)srow < 256u;
        const int  sslot = (srow + 4) & 3;
        const float* ssrc = xn + (size_t)sc0 * 65536 + (size_t)(rowok ? srow : 0) * 256;

        // stage cnt chunks starting at cbase (cnt is a literal at call sites)
        auto stage_chunks = [&](int cbase, int cnt) {
            if (!do_stage) return;
            float v[3][8];
            #pragma unroll
            for (int cc = 0; cc < 3; ++cc) {
                if (cc >= cnt) continue;
                int px = (cbase + cc) * 32 - 1 + lane;
                bool pok = rowok && (unsigned)px < 256u;
                #pragma unroll
                for (int j = 0; j < 8; ++j)
                    v[cc][j] = pok ? ssrc[j * 65536 + px] : 0.0f;
            }
            #pragma unroll
            for (int cc = 0; cc < 3; ++cc) {
                if (cc >= cnt) continue;
                int px = (cbase + cc) * 32 - 1 + lane;
                if (px <= 258) {
                    uint4 pk;
                    pk.x = pack_bf16x2(v[cc][0], v[cc][1]);
                    pk.y = pack_bf16x2(v[cc][2], v[cc][3]);
                    pk.z = pack_bf16x2(v[cc][4], v[cc][5]);
                    pk.w = pack_bf16x2(v[cc][6], v[cc][7]);
                    *reinterpret_cast<uint4*>(smem + SM_A + sslot * AROW + (px + 1) * PXS + sc0 * 2) = pk;
                }
            }
        };

        // acc init = bias (folds the bias add into the GEMM)
        float acc[2][8][4];
        #pragma unroll
        for (int mf = 0; mf < 2; ++mf)
            #pragma unroll
            for (int nf = 0; nf < 8; ++nf)
                #pragma unroll
                for (int j = 0; j < 4; ++j)
                    acc[mf][nf][j] = bs[nf * 8 + 2 * cq + (j & 1)];

        #pragma unroll
        for (int t = 0; t < 9; ++t) {
            const int r = t / 3, s = t % 3;          // fixed r-ascending order
            const int slot = (hrow + 3 + r) & 3;     // row hrow-1+r
            const uint32_t aBase = sb + SM_A + slot * AROW + (pxwbase + s) * PXS + aLane;
            const uint32_t bBase = sb + SM_B + t * 8192;
            #pragma unroll
            for (int kc = 0; kc < 4; ++kc) {
                uint32_t a[2][4];
                #pragma unroll
                for (int mf = 0; mf < 2; ++mf)
                    LDSM_X4(a[mf], aBase + mf * (16 * PXS) + kc * 32);
                uint32_t bb[16];
                #pragma unroll
                for (int nb = 0; nb < 4; ++nb) {
                    uint32_t off = (uint32_t)((rowb + nb * 16) * 128 + colb + kc * 32);
                    off ^= (off >> 3) & 0x70;
                    LDSM_X4(bb + nb * 4, bBase + off);
                }
                #pragma unroll
                for (int nb = 0; nb < 4; ++nb)
                    #pragma unroll
                    for (int mf = 0; mf < 2; ++mf) {
                        mma_bf16(acc[mf][2 * nb + 0], a[mf], bb + nb * 4 + 0);
                        mma_bf16(acc[mf][2 * nb + 1], a[mf], bb + nb * 4 + 2);
                    }
            }

            // ---- overlap hooks ----
            if (t == 2) BAR_SYNC(1);                 // slot(row hp-1) now dead
            if (t == 5) BAR_SYNC(2);                 // slot(row hp)   now dead
            if (grpA) {                              // stage row hp+3, steps 3..8
                if (t == 3) stage_chunks(0, 2);
                if (t == 4) stage_chunks(2, 2);
                if (t == 5) stage_chunks(4, 2);
                if (t == 6) stage_chunks(6, 1);
                if (t == 7) stage_chunks(7, 1);
                if (t == 8) stage_chunks(8, 1);
            } else {                                 // stage row hp+4, steps 6..8
                if (t == 6) stage_chunks(0, 3);
                if (t == 7) stage_chunks(3, 3);
                if (t == 8) stage_chunks(6, 3);
            }
        }

        // ---- epilogue: min over 64 k (bias already in acc) + tanh + store ----
        #pragma unroll
        for (int mf = 0; mf < 2; ++mf) {
            #pragma unroll
            for (int half = 0; half < 2; ++half) {
                float m = fminf(acc[mf][0][half * 2 + 0], acc[mf][0][half * 2 + 1]);
                #pragma unroll
                for (int nf = 1; nf < 8; ++nf)
                    m = fminf(m, fminf(acc[mf][nf][half * 2 + 0],
                                       acc[mf][nf][half * 2 + 1]));
                m = fminf(m, __shfl_xor_sync(0xFFFFFFFFu, m, 1));
                m = fminf(m, __shfl_xor_sync(0xFFFFFFFFu, m, 2));
                if (cq == 0) {
                    int px = pxwbase + mf * 16 + half * 8 + lrow;
                    out[(size_t)n * 65536 + (size_t)hrow * 256 + px] = tanhf(tanhf(m));
                }
            }
        }

        __syncthreads();   // staged rows visible; all reads done before next writes
    }
}

// ---------------- launch ---------------------------------------------------
extern "C" void kernel_launch(void* const* d_in, const int* in_sizes, int n_in,
                              void* d_out, int out_size) {
    const float* x = (const float*)d_in[0];
    const float* w = (const float*)d_in[1];
    const float* b = (const float*)d_in[2];
    float* out = (float*)d_out;

    cudaFuncSetAttribute(conv_mma_kernel,
                         cudaFuncAttributeMaxDynamicSharedMemorySize, SM_TOTAL);

    prep_w_kernel<<<(9 * 64 * 64 + 255) / 256, 256>>>(w);

    dim3 grid(32, 16);   // (h-strips of 8, n)
    conv_mma_kernel<<<grid, 512, SM_TOTAL>>>(x, b, out);
}